// round 10
// baseline (speedup 1.0000x reference)
#include <cuda_runtime.h>
#include <cstdint>

#define BATCH  16
#define TLEN   4096
#define DIM    512
#define CHUNK  32
#define MEMSZ  64
#define NSPLIT 8
#define DSLICE (DIM / NSPLIT)     // 64
#define NSTEP  (TLEN / CHUNK)     // 128
#define NBLK   (BATCH * NSPLIT)   // 128 blocks, all co-resident
#define NTHR   256
#define EPSF   1e-10f
#define NINST  (2 * NSTEP)        // barrier instances per launch

// ---- cross-block scratch (static __device__, allocation-free) ----
__device__ float    g_plog[BATCH][NSPLIT][CHUNK][MEMSZ]; // partial logits (1 MB)
__device__ float    g_pdot[BATCH][NSPLIT][MEMSZ];        // partial dot(new_m, mem_m)
__device__ float    g_pmm [BATCH][NSPLIT][MEMSZ];        // partial ||mem_m||^2
__device__ float    g_pnn [BATCH][NSPLIT];               // partial ||new_m||^2
__device__ float    g_ent [BATCH];                       // per-batch entropy
__device__ unsigned g_cntA[NINST][BATCH];                // level-A: per-batch arrival
__device__ unsigned g_cntB[NINST];                       // level-B: batch leaders

__global__ void zero_ctr_kernel() {
    int t = blockIdx.x * blockDim.x + threadIdx.x;
    if (t < NINST * BATCH) ((unsigned*)g_cntA)[t] = 0u;
    if (t < NINST)         g_cntB[t] = 0u;
}

// Two-level full-grid barrier, semantics identical to the proven single-counter
// version (fence -> arrive -> spin -> fence), per-instance counters (no reuse).
__device__ __forceinline__ void gbar2(int inst, int b, int s, int tid) {
    __syncthreads();
    __threadfence();
    if (tid == 0) {
        atomicAdd(&g_cntA[inst][b], 1u);
        if (s == 0) {
            const volatile unsigned* pa = &g_cntA[inst][b];
            while (*pa < (unsigned)NSPLIT) { }
            atomicAdd(&g_cntB[inst], 1u);
        }
        const volatile unsigned* pb = &g_cntB[inst];
        while (*pb < (unsigned)BATCH) { }
        __threadfence();
    }
    __syncthreads();
}

__global__ void __launch_bounds__(NTHR, 1)
memk(const float* __restrict__ x, const float* __restrict__ mem_init,
     float* __restrict__ out)
{
    __shared__ float memS  [DSLICE][MEMSZ + 4]; // [d][m]
    __shared__ float chunkS[DSLICE][CHUNK + 2]; // [d][c]
    __shared__ float logS  [CHUNK][MEMSZ];
    __shared__ float newm  [DSLICE];
    __shared__ float score [MEMSZ];
    __shared__ float msS   [MEMSZ];
    __shared__ float mfS   [MEMSZ];
    __shared__ float simS  [MEMSZ];
    __shared__ float sEntMean;
    __shared__ int   sRepl, sMerge;

    const int tid  = threadIdx.x;
    const int bid  = blockIdx.x;
    const int b    = bid / NSPLIT;
    const int s    = bid % NSPLIT;
    const int d0   = s * DSLICE;
    const int lane = tid & 31;
    const int warp = tid >> 5;

    // init mem slice: mem_init[b][m][d0+d] -> memS[d][m]
    for (int i = tid; i < DSLICE * MEMSZ; i += NTHR) {
        int m = i >> 6;
        int d = i & 63;
        memS[d][m] = mem_init[((size_t)b * MEMSZ + m) * DIM + d0 + d];
    }
    for (int i = tid; i < MEMSZ; i += NTHR) { msS[i] = 0.0f; mfS[i] = 0.0f; }

    const float scale = 1.0f / sqrtf((float)DIM);
    const float thr   = 0.5f * log2f((float)MEMSZ + EPSF);  // = 3.0

    const int i_c = tid >> 4;  // c pair base 2*i_c
    const int j_m = tid & 15;  // m quad base 4*j_m

    // chunk-load decomposition: thread owns q0 = tid and q1 = tid + 256
    const int q0_c = tid >> 4, q0_d = tid & 15;
    const int q1_c = (tid + 256) >> 4, q1_d = tid & 15;

    // prologue: fetch chunk 0 into registers
    float4 v0, v1;
    {
        const float* xb = x + ((size_t)b * TLEN) * DIM + d0;
        v0 = *(const float4*)(xb + (size_t)q0_c * DIM + q0_d * 4);
        v1 = *(const float4*)(xb + (size_t)q1_c * DIM + q1_d * 4);
    }
    __syncthreads();   // memS/msS/mfS init complete

    for (int step = 0; step < NSTEP; ++step) {
        // install chunk (registers -> SMEM, transposed) then sync
        chunkS[q0_d * 4 + 0][q0_c] = v0.x; chunkS[q0_d * 4 + 1][q0_c] = v0.y;
        chunkS[q0_d * 4 + 2][q0_c] = v0.z; chunkS[q0_d * 4 + 3][q0_c] = v0.w;
        chunkS[q1_d * 4 + 0][q1_c] = v1.x; chunkS[q1_d * 4 + 1][q1_c] = v1.y;
        chunkS[q1_d * 4 + 2][q1_c] = v1.z; chunkS[q1_d * 4 + 3][q1_c] = v1.w;
        __syncthreads();

        // ================= Phase 1 =================
        float a00 = 0, a01 = 0, a02 = 0, a03 = 0;
        float a10 = 0, a11 = 0, a12 = 0, a13 = 0;
        #pragma unroll 4
        for (int d = 0; d < DSLICE; ++d) {
            float2 av = *(const float2*)&chunkS[d][2 * i_c];
            float4 bv = *(const float4*)&memS[d][4 * j_m];
            a00 = fmaf(av.x, bv.x, a00);
            a01 = fmaf(av.x, bv.y, a01);
            a02 = fmaf(av.x, bv.z, a02);
            a03 = fmaf(av.x, bv.w, a03);
            a10 = fmaf(av.y, bv.x, a10);
            a11 = fmaf(av.y, bv.y, a11);
            a12 = fmaf(av.y, bv.z, a12);
            a13 = fmaf(av.y, bv.w, a13);
        }
        {
            float4 w0 = make_float4(a00, a01, a02, a03);
            float4 w1 = make_float4(a10, a11, a12, a13);
            __stcg((float4*)&g_plog[b][s][2 * i_c][4 * j_m],     w0);
            __stcg((float4*)&g_plog[b][s][2 * i_c + 1][4 * j_m], w1);
        }
        if (tid < DSLICE) {
            float mx = chunkS[tid][0];
            #pragma unroll
            for (int c = 1; c < CHUNK; ++c) mx = fmaxf(mx, chunkS[tid][c]);
            newm[tid] = mx;
        }
        __syncthreads();
        if (tid < MEMSZ) {
            float pd = 0.0f, pm = 0.0f;
            #pragma unroll 4
            for (int d = 0; d < DSLICE; ++d) {
                float mv = memS[d][tid];
                pd = fmaf(newm[d], mv, pd);
                pm = fmaf(mv, mv, pm);
            }
            __stcg(&g_pdot[b][s][tid], pd);
            __stcg(&g_pmm [b][s][tid], pm);
        } else if (tid < MEMSZ + 32) {
            int l = tid - MEMSZ;
            float n0 = newm[l], n1 = newm[l + 32];
            float nn = n0 * n0 + n1 * n1;
            #pragma unroll
            for (int o = 16; o; o >>= 1) nn += __shfl_xor_sync(0xffffffffu, nn, o);
            if (l == 0) __stcg(&g_pnn[b][s], nn);
        }

        // prefetch next chunk into registers; LDG latency hides under barrier
        if (step + 1 < NSTEP) {
            const float* xb = x + ((size_t)b * TLEN + (size_t)(step + 1) * CHUNK) * DIM + d0;
            v0 = *(const float4*)(xb + (size_t)q0_c * DIM + q0_d * 4);
            v1 = *(const float4*)(xb + (size_t)q1_c * DIM + q1_d * 4);
        }
        gbar2(2 * step, b, s, tid);

        // ================= Phase 2 (redundant per batch) =================
        for (int q = tid; q < CHUNK * (MEMSZ / 4); q += NTHR) {
            int c  = q >> 4;
            int mq = q & 15;
            float4 r = make_float4(0, 0, 0, 0);
            #pragma unroll
            for (int ss = 0; ss < NSPLIT; ++ss) {
                float4 t = __ldcg((const float4*)&g_plog[b][ss][c][mq * 4]);
                r.x += t.x; r.y += t.y; r.z += t.z; r.w += t.w;
            }
            *(float4*)&logS[c][4 * mq] = r;
        }
        __syncthreads();
        for (int c = warp; c < CHUNK; c += (NTHR / 32)) {
            float w0 = logS[c][lane]      * scale;
            float w1 = logS[c][lane + 32] * scale;
            float mx = fmaxf(w0, w1);
            #pragma unroll
            for (int o = 16; o; o >>= 1) mx = fmaxf(mx, __shfl_xor_sync(0xffffffffu, mx, o));
            float e0 = __expf(w0 - mx), e1 = __expf(w1 - mx);
            float sm = e0 + e1;
            #pragma unroll
            for (int o = 16; o; o >>= 1) sm += __shfl_xor_sync(0xffffffffu, sm, o);
            float inv = 1.0f / sm;
            logS[c][lane]      = e0 * inv;
            logS[c][lane + 32] = e1 * inv;
        }
        __syncthreads();
        if (tid < MEMSZ) {
            float sc = 0.0f;
            #pragma unroll
            for (int c = 0; c < CHUNK; ++c) sc += logS[c][tid];
            score[tid] = sc * (1.0f / CHUNK);
        } else if (tid < 2 * MEMSZ) {
            int m = tid - MEMSZ;
            float pd = 0.0f, pm = 0.0f, nn = 0.0f;
            #pragma unroll
            for (int ss = 0; ss < NSPLIT; ++ss) {
                pd += __ldcg(&g_pdot[b][ss][m]);
                pm += __ldcg(&g_pmm [b][ss][m]);
                nn += __ldcg(&g_pnn [b][ss]);
            }
            simS[m] = pd / (sqrtf(nn + 1e-8f) * sqrtf(pm + 1e-8f));
        }
        __syncthreads();
        if (warp == 0) {
            float s0 = score[lane], s1 = score[lane + 32];
            float e = -(log2f(s0 + EPSF) * s0 + log2f(s1 + EPSF) * s1);
            #pragma unroll
            for (int o = 16; o; o >>= 1) e += __shfl_xor_sync(0xffffffffu, e, o);
            if (lane == 0 && s == 0) __stcg(&g_ent[b], e);
        } else if (warp == 1) {
            float r0 = (msS[lane]      + score[lane])      / (mfS[lane]      + 1.0f);
            float r1 = (msS[lane + 32] + score[lane + 32]) / (mfS[lane + 32] + 1.0f);
            float v; int idx;
            if (r1 < r0) { v = r1; idx = lane + 32; } else { v = r0; idx = lane; }
            #pragma unroll
            for (int o = 16; o; o >>= 1) {
                float ov = __shfl_xor_sync(0xffffffffu, v, o);
                int   oi = __shfl_xor_sync(0xffffffffu, idx, o);
                if (ov < v || (ov == v && oi < idx)) { v = ov; idx = oi; }
            }
            if (lane == 0) sRepl = idx;
        } else if (warp == 2) {
            float w0 = simS[lane], w1 = simS[lane + 32];
            float v; int idx;
            if (w1 > w0) { v = w1; idx = lane + 32; } else { v = w0; idx = lane; }
            #pragma unroll
            for (int o = 16; o; o >>= 1) {
                float ov = __shfl_xor_sync(0xffffffffu, v, o);
                int   oi = __shfl_xor_sync(0xffffffffu, idx, o);
                if (ov > v || (ov == v && oi < idx)) { v = ov; idx = oi; }
            }
            if (lane == 0) sMerge = idx;
        }
        gbar2(2 * step + 1, b, s, tid);

        // ================= Phase 3 =================
        if (tid == 0) {
            float em = 0.0f;
            #pragma unroll
            for (int bb = 0; bb < BATCH; ++bb) em += __ldcg(&g_ent[bb]);
            sEntMean = em * (1.0f / BATCH);
        }
        __syncthreads();
        if (sEntMean > thr) {
            int rm = sRepl;
            if (tid < DSLICE) {
                memS[tid][rm] = newm[tid];
            } else if (tid < DSLICE + MEMSZ) {
                int m = tid - DSLICE;
                float sn = msS[m] + score[m];
                float fn = mfS[m] + 1.0f;
                if (m == rm) { sn = 0.0f; fn = 1.0f; }
                msS[m] = sn; mfS[m] = fn;
            }
        } else {
            int im = sMerge;
            if (tid < DSLICE) {
                float old = memS[tid][im];
                memS[tid][im] = old + (0.7f * newm[tid] - 0.7f * old);
            }
        }
        __syncthreads();
    }

    // write final mem slice
    for (int i = tid; i < MEMSZ * DSLICE; i += NTHR) {
        int m = i >> 6;
        int d = i & 63;
        out[((size_t)b * MEMSZ + m) * DIM + d0 + d] = memS[d][m];
    }
}

extern "C" void kernel_launch(void* const* d_in, const int* in_sizes, int n_in,
                              void* d_out, int out_size) {
    const float* x        = (const float*)d_in[0];
    const float* mem_init = (const float*)d_in[1];
    if (n_in >= 2 && in_sizes[0] < in_sizes[1]) {
        const float* t = x; x = mem_init; mem_init = t;
    }
    float* out = (float*)d_out;

    zero_ctr_kernel<<<9, 512>>>();
    memk<<<NBLK, NTHR>>>(x, mem_init, out);
}

// round 12
// speedup vs baseline: 1.2647x; 1.2647x over previous
#include <cuda_runtime.h>
#include <cstdint>

#define BATCH  16
#define TLEN   4096
#define DIM    512
#define CHUNK  32
#define MEMSZ  64
#define NSPLIT 8
#define DSLICE (DIM / NSPLIT)     // 64
#define NSTEP  (TLEN / CHUNK)     // 128
#define NBLK   (BATCH * NSPLIT)   // 128 blocks, all co-resident
#define NTHR   256
#define EPSF   1e-10f

// ---- cross-block scratch (parity double-buffered) ----
__device__ float    g_plog[2][BATCH][NSPLIT][CHUNK][MEMSZ];
__device__ float    g_pdot[2][BATCH][NSPLIT][MEMSZ];
__device__ float    g_pmm [2][BATCH][NSPLIT][MEMSZ];
__device__ float    g_pnn [2][BATCH][NSPLIT];
__device__ float    g_ent [NSTEP][BATCH];    // entropy: payload == ready flag (never 0.0)
__device__ unsigned g_cnt [NSTEP][BATCH];    // per-(step,batch) arrival counter

__global__ void zero_flags_kernel() {
    int t = blockIdx.x * blockDim.x + threadIdx.x;
    if (t < NSTEP * BATCH) {
        ((float*)g_ent)[t]    = 0.0f;
        ((unsigned*)g_cnt)[t] = 0u;
    }
}

__global__ void __launch_bounds__(NTHR, 1)
memk(const float* __restrict__ x, const float* __restrict__ mem_init,
     float* __restrict__ out)
{
    __shared__ float memS  [DSLICE][MEMSZ + 4]; // [d][m], pitch 68 (16B-aligned rows)
    __shared__ float chunkS[DSLICE][CHUNK + 4]; // [d][c], pitch 36 (16B-aligned rows!)
    __shared__ float logS  [CHUNK][MEMSZ];
    __shared__ float newm  [DSLICE];
    __shared__ float score [MEMSZ];
    __shared__ float msS   [MEMSZ];
    __shared__ float mfS   [MEMSZ];
    __shared__ float simS  [MEMSZ];
    __shared__ float entS  [BATCH];
    __shared__ int   sRepl, sMerge;

    const int tid  = threadIdx.x;
    const int bid  = blockIdx.x;
    const int b    = bid / NSPLIT;
    const int s    = bid % NSPLIT;
    const int d0   = s * DSLICE;
    const int lane = tid & 31;
    const int warp = tid >> 5;

    // init mem slice: mem_init[b][m][d0+d] -> memS[d][m]
    for (int i = tid; i < DSLICE * MEMSZ; i += NTHR) {
        int m = i >> 6;
        int d = i & 63;
        memS[d][m] = mem_init[((size_t)b * MEMSZ + m) * DIM + d0 + d];
    }
    for (int i = tid; i < MEMSZ; i += NTHR) { msS[i] = 0.0f; mfS[i] = 0.0f; }

    const float scale = 1.0f / sqrtf((float)DIM);
    const float thr   = 0.5f * log2f((float)MEMSZ + EPSF);  // = 3.0

    // GEMM 4c x 4m tile on warps 0-3 (128 threads)
    const int i_c = tid >> 4;   // 0..7  -> c base 4*i_c   (valid when tid < 128)
    const int j_m = tid & 15;   // 0..15 -> m base 4*j_m

    // chunk-load decomposition (prefetch): thread owns q0 = tid, q1 = tid + 256
    const int q0_c = tid >> 4,         q0_d = tid & 15;
    const int q1_c = (tid + 256) >> 4, q1_d = tid & 15;

    // prologue: fetch chunk 0 into registers
    float4 v0, v1;
    {
        const float* xb = x + ((size_t)b * TLEN) * DIM + d0;
        v0 = *(const float4*)(xb + (size_t)q0_c * DIM + q0_d * 4);
        v1 = *(const float4*)(xb + (size_t)q1_c * DIM + q1_d * 4);
    }
    __syncthreads();   // memS/msS/mfS init complete

    for (int step = 0; step < NSTEP; ++step) {
        const int p = step & 1;

        // install chunk (registers -> SMEM, transposed [d][c]) then sync
        chunkS[q0_d * 4 + 0][q0_c] = v0.x; chunkS[q0_d * 4 + 1][q0_c] = v0.y;
        chunkS[q0_d * 4 + 2][q0_c] = v0.z; chunkS[q0_d * 4 + 3][q0_c] = v0.w;
        chunkS[q1_d * 4 + 0][q1_c] = v1.x; chunkS[q1_d * 4 + 1][q1_c] = v1.y;
        chunkS[q1_d * 4 + 2][q1_c] = v1.z; chunkS[q1_d * 4 + 3][q1_c] = v1.w;
        __syncthreads();

        // ================= Phase 1 =================
        if (tid < 128) {
            // 4x4 register tile; each output keeps the exact d=0..63 fmaf chain
            float a0x=0,a0y=0,a0z=0,a0w=0, a1x=0,a1y=0,a1z=0,a1w=0;
            float a2x=0,a2y=0,a2z=0,a2w=0, a3x=0,a3y=0,a3z=0,a3w=0;
            #pragma unroll 4
            for (int d = 0; d < DSLICE; ++d) {
                float4 cv = *(const float4*)&chunkS[d][4 * i_c];
                float4 mv = *(const float4*)&memS[d][4 * j_m];
                a0x = fmaf(cv.x, mv.x, a0x); a0y = fmaf(cv.x, mv.y, a0y);
                a0z = fmaf(cv.x, mv.z, a0z); a0w = fmaf(cv.x, mv.w, a0w);
                a1x = fmaf(cv.y, mv.x, a1x); a1y = fmaf(cv.y, mv.y, a1y);
                a1z = fmaf(cv.y, mv.z, a1z); a1w = fmaf(cv.y, mv.w, a1w);
                a2x = fmaf(cv.z, mv.x, a2x); a2y = fmaf(cv.z, mv.y, a2y);
                a2z = fmaf(cv.z, mv.z, a2z); a2w = fmaf(cv.z, mv.w, a2w);
                a3x = fmaf(cv.w, mv.x, a3x); a3y = fmaf(cv.w, mv.y, a3y);
                a3z = fmaf(cv.w, mv.z, a3z); a3w = fmaf(cv.w, mv.w, a3w);
            }
            __stcg((float4*)&g_plog[p][b][s][4 * i_c + 0][4 * j_m], make_float4(a0x, a0y, a0z, a0w));
            __stcg((float4*)&g_plog[p][b][s][4 * i_c + 1][4 * j_m], make_float4(a1x, a1y, a1z, a1w));
            __stcg((float4*)&g_plog[p][b][s][4 * i_c + 2][4 * j_m], make_float4(a2x, a2y, a2z, a2w));
            __stcg((float4*)&g_plog[p][b][s][4 * i_c + 3][4 * j_m], make_float4(a3x, a3y, a3z, a3w));
        } else if (tid < 128 + DSLICE) {
            // newm in parallel with GEMM; exact serial c-chain
            int d = tid - 128;
            float mx = chunkS[d][0];
            #pragma unroll
            for (int c = 1; c < CHUNK; ++c) mx = fmaxf(mx, chunkS[d][c]);
            newm[d] = mx;
        }
        __syncthreads();
        if (tid < MEMSZ) {
            float pd = 0.0f, pm = 0.0f;
            #pragma unroll 4
            for (int d = 0; d < DSLICE; ++d) {
                float mv = memS[d][tid];
                pd = fmaf(newm[d], mv, pd);
                pm = fmaf(mv, mv, pm);
            }
            __stcg(&g_pdot[p][b][s][tid], pd);
            __stcg(&g_pmm [p][b][s][tid], pm);
        } else if (tid < MEMSZ + 32) {
            int l = tid - MEMSZ;
            float n0 = newm[l], n1 = newm[l + 32];
            float nn = n0 * n0 + n1 * n1;
            #pragma unroll
            for (int o = 16; o; o >>= 1) nn += __shfl_xor_sync(0xffffffffu, nn, o);
            if (l == 0) __stcg(&g_pnn[p][b][s], nn);
        }

        // prefetch next chunk; LDG latency hides under barrier + phase 2
        if (step + 1 < NSTEP) {
            const float* xb = x + ((size_t)b * TLEN + (size_t)(step + 1) * CHUNK) * DIM + d0;
            v0 = *(const float4*)(xb + (size_t)q0_c * DIM + q0_d * 4);
            v1 = *(const float4*)(xb + (size_t)q1_c * DIM + q1_d * 4);
        }

        // per-batch barrier: producers release, tid0 spins for 8 siblings
        __threadfence();
        __syncthreads();
        if (tid == 0) {
            atomicAdd(&g_cnt[step][b], 1u);
            const volatile unsigned* pc = &g_cnt[step][b];
            while (*pc < (unsigned)NSPLIT) { }
            __threadfence();
        }
        __syncthreads();

        // ================= Phase 2 (redundant per batch; arithmetic exact) ====
        for (int q = tid; q < CHUNK * (MEMSZ / 4); q += NTHR) {
            int c  = q >> 4;
            int mq = q & 15;
            float4 r = make_float4(0, 0, 0, 0);
            #pragma unroll
            for (int ss = 0; ss < NSPLIT; ++ss) {
                float4 t = __ldcg((const float4*)&g_plog[p][b][ss][c][mq * 4]);
                r.x += t.x; r.y += t.y; r.z += t.z; r.w += t.w;
            }
            *(float4*)&logS[c][4 * mq] = r;
        }
        __syncthreads();
        for (int c = warp; c < CHUNK; c += (NTHR / 32)) {
            float w0 = logS[c][lane]      * scale;
            float w1 = logS[c][lane + 32] * scale;
            float mx = fmaxf(w0, w1);
            #pragma unroll
            for (int o = 16; o; o >>= 1) mx = fmaxf(mx, __shfl_xor_sync(0xffffffffu, mx, o));
            float e0 = __expf(w0 - mx), e1 = __expf(w1 - mx);
            float sm = e0 + e1;
            #pragma unroll
            for (int o = 16; o; o >>= 1) sm += __shfl_xor_sync(0xffffffffu, sm, o);
            float inv = 1.0f / sm;
            logS[c][lane]      = e0 * inv;
            logS[c][lane + 32] = e1 * inv;
        }
        __syncthreads();
        if (tid < MEMSZ) {
            float sc = 0.0f;
            #pragma unroll
            for (int c = 0; c < CHUNK; ++c) sc += logS[c][tid];   // exact serial order
            score[tid] = sc * (1.0f / CHUNK);
        } else if (tid < 2 * MEMSZ) {
            int m = tid - MEMSZ;
            float pd = 0.0f, pm = 0.0f, nn = 0.0f;
            #pragma unroll
            for (int ss = 0; ss < NSPLIT; ++ss) {
                pd += __ldcg(&g_pdot[p][b][ss][m]);
                pm += __ldcg(&g_pmm [p][b][ss][m]);
                nn += __ldcg(&g_pnn [p][b][ss]);
            }
            simS[m] = pd / (sqrtf(nn + 1e-8f) * sqrtf(pm + 1e-8f));
        }
        __syncthreads();
        if (warp == 0) {
            float s0 = score[lane], s1 = score[lane + 32];
            float e = -(log2f(s0 + EPSF) * s0 + log2f(s1 + EPSF) * s1);
            #pragma unroll
            for (int o = 16; o; o >>= 1) e += __shfl_xor_sync(0xffffffffu, e, o);
            if (lane == 0 && s == 0) __stcg(&g_ent[step][b], e);
        } else if (warp == 1) {
            float r0 = (msS[lane]      + score[lane])      / (mfS[lane]      + 1.0f);
            float r1 = (msS[lane + 32] + score[lane + 32]) / (mfS[lane + 32] + 1.0f);
            float v; int idx;
            if (r1 < r0) { v = r1; idx = lane + 32; } else { v = r0; idx = lane; }
            #pragma unroll
            for (int o = 16; o; o >>= 1) {
                float ov = __shfl_xor_sync(0xffffffffu, v, o);
                int   oi = __shfl_xor_sync(0xffffffffu, idx, o);
                if (ov < v || (ov == v && oi < idx)) { v = ov; idx = oi; }
            }
            if (lane == 0) sRepl = idx;
        } else if (warp == 2) {
            float w0 = simS[lane], w1 = simS[lane + 32];
            float v; int idx;
            if (w1 > w0) { v = w1; idx = lane + 32; } else { v = w0; idx = lane; }
            #pragma unroll
            for (int o = 16; o; o >>= 1) {
                float ov = __shfl_xor_sync(0xffffffffu, v, o);
                int   oi = __shfl_xor_sync(0xffffffffu, idx, o);
                if (ov > v || (ov == v && oi < idx)) { v = ov; idx = oi; }
            }
            if (lane == 0) sMerge = idx;
        } else if (warp == 3 && lane < BATCH) {
            // cross-batch entropy: payload-as-flag spin on per-step slots
            const volatile float* pe = &g_ent[step][lane];
            float v;
            do { v = *pe; } while (v == 0.0f);
            entS[lane] = v;
        }
        __syncthreads();

        // ================= Phase 3 =================
        float em = 0.0f;
        #pragma unroll
        for (int bb = 0; bb < BATCH; ++bb) em += entS[bb];   // exact serial order
        em *= (1.0f / BATCH);

        if (em > thr) {
            int rm = sRepl;
            if (tid < DSLICE) {
                memS[tid][rm] = newm[tid];
            } else if (tid < DSLICE + MEMSZ) {
                int m = tid - DSLICE;
                float sn = msS[m] + score[m];
                float fn = mfS[m] + 1.0f;
                if (m == rm) { sn = 0.0f; fn = 1.0f; }
                msS[m] = sn; mfS[m] = fn;
            }
        } else {
            int im = sMerge;
            if (tid < DSLICE) {
                float old = memS[tid][im];
                memS[tid][im] = old + (0.7f * newm[tid] - 0.7f * old);
            }
        }
        __syncthreads();
    }

    // write final mem slice
    for (int i = tid; i < MEMSZ * DSLICE; i += NTHR) {
        int m = i >> 6;
        int d = i & 63;
        out[((size_t)b * MEMSZ + m) * DIM + d0 + d] = memS[d][m];
    }
}

extern "C" void kernel_launch(void* const* d_in, const int* in_sizes, int n_in,
                              void* d_out, int out_size) {
    const float* x        = (const float*)d_in[0];
    const float* mem_init = (const float*)d_in[1];
    if (n_in >= 2 && in_sizes[0] < in_sizes[1]) {
        const float* t = x; x = mem_init; mem_init = t;
    }
    float* out = (float*)d_out;

    zero_flags_kernel<<<4, 512>>>();
    memk<<<NBLK, NTHR>>>(x, mem_init, out);
}